// round 5
// baseline (speedup 1.0000x reference)
#include <cuda_runtime.h>

#define RES 512
#define BATCH 128
#define NC 10
#define CH 32                      // images per L2-resident chunk (67 MB < 126 MB L2)
#define WBUF 576                   // per-warp padded 512-elt buffer (IDX(511)=574 < 576)
#define IDX(i) ((i) + ((i) >> 3))

// ---- device-global scratch (allocation-free rule) ----
__device__ float2 g_field[(size_t)BATCH * RES * RES];
__device__ float  g_partial[(size_t)BATCH * RES * NC];
__device__ float2 g_phexp[(size_t)3 * RES * RES];  // exp(i*phase), layer-major
__device__ float2 g_gx[RES];    // exp(-i*pi*lam*z*fx^2)
__device__ float2 g_gcol[RES];  // exp(i*K*Z)*exp(-i*pi*lam*z*fy^2) / (RES*RES)

__device__ __forceinline__ float2 cmul(float2 a, float2 b) {
    return make_float2(fmaf(a.x, b.x, -a.y * b.y), fmaf(a.x, b.y, a.y * b.x));
}
__device__ __forceinline__ float2 cadd(float2 a, float2 b) { return make_float2(a.x + b.x, a.y + b.y); }
__device__ __forceinline__ float2 csub(float2 a, float2 b) { return make_float2(a.x - b.x, a.y - b.y); }
__device__ __forceinline__ float2 cconj(float2 a) { return make_float2(a.x, -a.y); }
__device__ __forceinline__ float2 mul_mi(float2 a) { return make_float2(a.y, -a.x); }  // * -i
__device__ __forceinline__ float2 mul_pi(float2 a) { return make_float2(-a.y, a.x); }  // * +i

// Natural-order DFT-8, W = exp(-2*pi*i/8)
__device__ __forceinline__ void dft8(float2 v[8]) {
    const float S = 0.70710678118654752440f;
    float2 a00 = cadd(v[0], v[4]), a01 = csub(v[0], v[4]);
    float2 a10 = cadd(v[1], v[5]), a11 = csub(v[1], v[5]);
    float2 a20 = cadd(v[2], v[6]), a21 = csub(v[2], v[6]);
    float2 a30 = cadd(v[3], v[7]), a31 = csub(v[3], v[7]);
    float2 b00 = cadd(a00, a20), b02 = csub(a00, a20);
    float2 b01 = cadd(a01, mul_mi(a21)), b03 = cadd(a01, mul_pi(a21));
    float2 b10 = cadd(a10, a30), b12 = csub(a10, a30);
    float2 b11 = cadd(a11, mul_mi(a31)), b13 = cadd(a11, mul_pi(a31));
    float2 w1b11 = make_float2(S * (b11.x + b11.y), S * (b11.y - b11.x));   // W^1 * b11
    float2 w3b13 = make_float2(S * (b13.y - b13.x), -S * (b13.x + b13.y));  // W^3 * b13
    v[0] = cadd(b00, b10);          v[4] = csub(b00, b10);
    v[1] = cadd(b01, w1b11);        v[5] = csub(b01, w1b11);
    v[2] = cadd(b02, mul_mi(b12));  v[6] = cadd(b02, mul_pi(b12));
    v[3] = cadd(b03, w3b13);        v[7] = csub(b03, w3b13);
}

// ---- WARP-PRIVATE 512-pt radix-8 Stockham FFT ----
// One warp per FFT. Lane l owns streams j1=l (va) and j2=l+32 (vb), each 8 regs,
// element (j + 64*r) natural order. Single per-warp smem buffer A; the two
// streams write disjoint slots. Only __syncwarp() needed between phases.
__device__ __forceinline__ void fft512_warp(float2 va[8], float2 vb[8], int l, float2* A) {
    const int j1 = l, j2 = l + 32;
    dft8(va); dft8(vb);
    __syncwarp();                    // WAR vs this warp's previous reads of A
#pragma unroll
    for (int r = 0; r < 8; r++) { A[IDX(8 * j1 + r)] = va[r]; A[IDX(8 * j2 + r)] = vb[r]; }
    __syncwarp();
#pragma unroll
    for (int r = 0; r < 8; r++) { va[r] = A[IDX(j1 + 64 * r)]; vb[r] = A[IDX(j2 + 64 * r)]; }
    {   // stage-1 twiddle: exp(-2*pi*i*(j&7)/64) — identical for j1 and j2
        float ang = -6.2831853071795864769f * (float)(l & 7) * (1.0f / 64.0f);
        float s, c; __sincosf(ang, &s, &c);
        float2 w = make_float2(c, s), wr = w;
#pragma unroll
        for (int r = 1; r < 8; r++) { va[r] = cmul(va[r], wr); vb[r] = cmul(vb[r], wr); wr = cmul(wr, w); }
    }
    dft8(va); dft8(vb);
    __syncwarp();
#pragma unroll
    for (int r = 0; r < 8; r++) {
        A[IDX(((j1 >> 3) << 6) + (j1 & 7) + 8 * r)] = va[r];
        A[IDX(((j2 >> 3) << 6) + (j2 & 7) + 8 * r)] = vb[r];
    }
    __syncwarp();
#pragma unroll
    for (int r = 0; r < 8; r++) { va[r] = A[IDX(j1 + 64 * r)]; vb[r] = A[IDX(j2 + 64 * r)]; }
    {   // stage-2 twiddles: exp(-2*pi*i*j/512), distinct for j1 / j2
        float ang1 = -6.2831853071795864769f * (float)j1 * (1.0f / 512.0f);
        float ang2 = -6.2831853071795864769f * (float)j2 * (1.0f / 512.0f);
        float s1, c1, s2, c2;
        __sincosf(ang1, &s1, &c1);
        __sincosf(ang2, &s2, &c2);
        float2 w1 = make_float2(c1, s1), wr1 = w1;
        float2 w2 = make_float2(c2, s2), wr2 = w2;
#pragma unroll
        for (int r = 1; r < 8; r++) {
            va[r] = cmul(va[r], wr1); wr1 = cmul(wr1, w1);
            vb[r] = cmul(vb[r], wr2); wr2 = cmul(wr2, w2);
        }
    }
    dft8(va); dft8(vb);
    // va[r] = X[l + 64r], vb[r] = X[l + 32 + 64r]
}

// ---- table init (fp64 phase to match numpy's float64 H) ----
__global__ void k_init() {
    int f = threadIdx.x;
    if (f >= RES) return;
    const double PI = 3.14159265358979323846;
    const double lam = 5.32e-07, z = 0.035, dx = 1e-06;
    double fx = ((f < RES / 2) ? (double)f : (double)(f - RES)) / ((double)RES * dx);
    double ang = -PI * lam * z * fx * fx;
    double s, c;
    sincos(ang, &s, &c);
    g_gx[f] = make_float2((float)c, (float)s);
    double kz = (2.0 * PI / lam) * z;
    double s2, c2;
    sincos(ang + kz, &s2, &c2);
    double inv = 1.0 / ((double)RES * (double)RES);
    g_gcol[f] = make_float2((float)(c2 * inv), (float)(s2 * inv));
}

// ---- phase exponential precompute: g_phexp = exp(i*phases) ----
__global__ void k_phexp(const float* __restrict__ phases) {
    size_t i = (size_t)blockIdx.x * 1024 + threadIdx.x;
    float s, c;
    __sincosf(phases[i], &s, &c);
    g_phexp[i] = make_float2(c, s);
}

// ---- layer-0 row pass: x * e^{i phi0} -> FFT -> * g(fx); 1 warp = 1 row ----
__global__ void __launch_bounds__(128, 5)
k_row_first(const float* __restrict__ x, int row0) {
    extern __shared__ float2 sm[];
    const int w = threadIdx.x >> 5, l = threadIdx.x & 31;
    const int row = row0 + blockIdx.x * 4 + w;
    const int y = row & 511;
    const float* xr = x + (size_t)row * RES;
    const float2* pe = g_phexp + (size_t)y * RES;
    float2* A = sm + (size_t)w * WBUF;
    float2 va[8], vb[8];
#pragma unroll
    for (int r = 0; r < 8; r++) {
        int i1 = l + 64 * r, i2 = i1 + 32;
        float2 e1 = pe[i1], e2 = pe[i2];
        float x1 = xr[i1], x2 = xr[i2];
        va[r] = make_float2(x1 * e1.x, x1 * e1.y);
        vb[r] = make_float2(x2 * e2.x, x2 * e2.y);
    }
    fft512_warp(va, vb, l, A);
    float2* outrow = g_field + (size_t)row * RES;
#pragma unroll
    for (int r = 0; r < 8; r++) {
        int f1 = l + 64 * r, f2 = f1 + 32;
        outrow[f1] = cmul(va[r], g_gx[f1]);
        outrow[f2] = cmul(vb[r], g_gx[f2]);
    }
}

// ---- mid row pass: unnorm IFFT -> * e^{i phi} -> FFT -> * g(fx); 1 warp = 1 row ----
__global__ void __launch_bounds__(128, 5)
k_row_mid(int layer, int row0) {
    extern __shared__ float2 sm[];
    const int w = threadIdx.x >> 5, l = threadIdx.x & 31;
    const int row = row0 + blockIdx.x * 4 + w;
    const int y = row & 511;
    const float2* pe = g_phexp + (size_t)layer * RES * RES + (size_t)y * RES;
    float2* A = sm + (size_t)w * WBUF;
    float2* inrow = g_field + (size_t)row * RES;
    float2 va[8], vb[8];
#pragma unroll
    for (int r = 0; r < 8; r++) {
        int i1 = l + 64 * r;
        va[r] = cconj(inrow[i1]);        // IFFT via conj-FFT-conj
        vb[r] = cconj(inrow[i1 + 32]);
    }
    fft512_warp(va, vb, l, A);
#pragma unroll
    for (int r = 0; r < 8; r++) {
        int i1 = l + 64 * r, i2 = i1 + 32;
        va[r] = cmul(cconj(va[r]), pe[i1]);
        vb[r] = cmul(cconj(vb[r]), pe[i2]);
    }
    fft512_warp(va, vb, l, A);
#pragma unroll
    for (int r = 0; r < 8; r++) {
        int f1 = l + 64 * r, f2 = f1 + 32;
        inrow[f1] = cmul(va[r], g_gx[f1]);
        inrow[f2] = cmul(vb[r], g_gx[f2]);
    }
}

// ---- column pass: FFT(col) -> * gcol -> unnorm IFFT(col); 1 warp = 1 column ----
__global__ void __launch_bounds__(256, 2)
k_col(int b0) {
    extern __shared__ float2 sm[];
    const int tid = threadIdx.x;
    const int w = tid >> 5, l = tid & 31;
    const int b = b0 + blockIdx.x;
    const int c0 = blockIdx.y * 8;
    float2* base = g_field + (size_t)b * RES * RES + c0;
    // cooperative transposed load: 8 consecutive threads read 8 consecutive cols (64B)
#pragma unroll
    for (int i = 0; i < 16; i++) {
        int rowi = i * 32 + (tid >> 3);
        int cc = tid & 7;
        sm[(size_t)cc * WBUF + IDX(rowi)] = base[(size_t)rowi * RES + cc];
    }
    __syncthreads();
    float2* A = sm + (size_t)w * WBUF;   // warp w <-> column c0+w
    float2 va[8], vb[8];
#pragma unroll
    for (int r = 0; r < 8; r++) { va[r] = A[IDX(l + 64 * r)]; vb[r] = A[IDX(l + 32 + 64 * r)]; }
    fft512_warp(va, vb, l, A);
#pragma unroll
    for (int r = 0; r < 8; r++) {
        int f1 = l + 64 * r, f2 = f1 + 32;
        va[r] = cconj(cmul(va[r], g_gcol[f1]));
        vb[r] = cconj(cmul(vb[r], g_gcol[f2]));
    }
    fft512_warp(va, vb, l, A);
    __syncwarp();
    // each lane rewrites exactly the slots it read in the last stage — lane-local
#pragma unroll
    for (int r = 0; r < 8; r++) {
        A[IDX(l + 64 * r)] = cconj(va[r]);
        A[IDX(l + 32 + 64 * r)] = cconj(vb[r]);
    }
    __syncthreads();
#pragma unroll
    for (int i = 0; i < 16; i++) {
        int rowi = i * 32 + (tid >> 3);
        int cc = tid & 7;
        base[(size_t)rowi * RES + cc] = sm[(size_t)cc * WBUF + IDX(rowi)];
    }
}

// ---- final row pass: unnorm IFFT(row) -> intensity -> per-row dot with fc_w ----
__global__ void __launch_bounds__(128, 5)
k_row_final(const float* __restrict__ fc_w, int row0) {
    extern __shared__ float2 sm[];
    const int w = threadIdx.x >> 5, l = threadIdx.x & 31;
    const int row = row0 + blockIdx.x * 4 + w;
    const int y = row & 511;
    float2* A = sm + (size_t)w * WBUF;
    float2* inrow = g_field + (size_t)row * RES;
    float2 va[8], vb[8];
#pragma unroll
    for (int r = 0; r < 8; r++) {
        int i1 = l + 64 * r;
        va[r] = cconj(inrow[i1]);
        vb[r] = cconj(inrow[i1 + 32]);
    }
    fft512_warp(va, vb, l, A);   // |conj(.)|^2 == |.|^2, skip final conj
    float acc[NC];
#pragma unroll
    for (int c = 0; c < NC; c++) acc[c] = 0.0f;
#pragma unroll
    for (int r = 0; r < 8; r++) {
        int i1 = l + 64 * r, i2 = i1 + 32;
        float I1 = va[r].x * va[r].x + va[r].y * va[r].y;
        float I2 = vb[r].x * vb[r].x + vb[r].y * vb[r].y;
        size_t col1 = (size_t)y * RES + i1;
#pragma unroll
        for (int c = 0; c < NC; c++) {
            const float* fw = fc_w + (size_t)c * (RES * RES);
            acc[c] += I1 * fw[col1] + I2 * fw[col1 + 32];
        }
    }
#pragma unroll
    for (int c = 0; c < NC; c++) {
#pragma unroll
        for (int off = 16; off > 0; off >>= 1)
            acc[c] += __shfl_down_sync(0xffffffffu, acc[c], off);
    }
    if (l == 0) {
#pragma unroll
        for (int c = 0; c < NC; c++) g_partial[(size_t)row * NC + c] = acc[c];
    }
}

// ---- final reduce: out[b][c] = fc_b[c] + sum_y partial[b*512+y][c] ----
__global__ void k_fc_reduce(const float* __restrict__ fc_b, float* __restrict__ out) {
    const int b = blockIdx.x;
    const int w = threadIdx.x >> 5;
    const int l = threadIdx.x & 31;
    if (w >= NC) return;
    float s = 0.0f;
    for (int y = l; y < RES; y += 32)
        s += g_partial[((size_t)(b << 9) + y) * NC + w];
#pragma unroll
    for (int off = 16; off > 0; off >>= 1)
        s += __shfl_down_sync(0xffffffffu, s, off);
    if (l == 0) out[b * NC + w] = s + fc_b[w];
}

extern "C" void kernel_launch(void* const* d_in, const int* in_sizes, int n_in,
                              void* d_out, int out_size) {
    (void)in_sizes; (void)n_in; (void)out_size;
    const float* x      = (const float*)d_in[0];
    const float* phases = (const float*)d_in[1];
    const float* fc_w   = (const float*)d_in[2];
    const float* fc_b   = (const float*)d_in[3];
    float* out = (float*)d_out;

    const size_t SMEM_ROW = (size_t)4 * WBUF * sizeof(float2);   // 18432 B (4 warps)
    const size_t SMEM_COL = (size_t)8 * WBUF * sizeof(float2);   // 36864 B (8 warps)
    const int ROW_BLOCKS = CH * RES / 4;                         // 4096 per chunk
    const int N_CHUNKS = BATCH / CH;                             // 4

    k_init<<<1, RES>>>();
    k_phexp<<<3 * RES * RES / 1024, 1024>>>(phases);
    // Whole 7-pass pipeline per 32-image chunk: working set stays in L2.
    for (int c = 0; c < N_CHUNKS; c++) {
        const int b0 = c * CH;
        const int row0 = b0 * RES;
        k_row_first<<<ROW_BLOCKS, 128, SMEM_ROW>>>(x, row0);
        for (int layer = 0; layer < 3; layer++) {
            k_col<<<dim3(CH, RES / 8), 256, SMEM_COL>>>(b0);
            if (layer < 2)
                k_row_mid<<<ROW_BLOCKS, 128, SMEM_ROW>>>(layer + 1, row0);
        }
        k_row_final<<<ROW_BLOCKS, 128, SMEM_ROW>>>(fc_w, row0);
    }
    k_fc_reduce<<<BATCH, 320>>>(fc_b, out);
}

// round 6
// speedup vs baseline: 1.0282x; 1.0282x over previous
#include <cuda_runtime.h>

#define RES 512
#define BATCH 128
#define NC 10
#define CH 32                      // images per L2-resident chunk (67 MB < 126 MB L2)
#define BUFSZ 581                  // 576 (padded 512) + 5: buffer-to-buffer bank decorrelation
#define IDX(i) ((i) + ((i) >> 3))

// ---- device-global scratch (allocation-free rule) ----
__device__ float2 g_field[(size_t)BATCH * RES * RES];
__device__ float  g_partial[(size_t)BATCH * RES * NC];
__device__ float2 g_phexp[(size_t)3 * RES * RES];  // exp(i*phase), layer-major
__device__ float2 g_gx[RES];    // exp(-i*pi*lam*z*fx^2)
__device__ float2 g_gcol[RES];  // exp(i*K*Z)*exp(-i*pi*lam*z*fy^2) / (RES*RES)

__device__ __forceinline__ float2 cmul(float2 a, float2 b) {
    return make_float2(fmaf(a.x, b.x, -a.y * b.y), fmaf(a.x, b.y, a.y * b.x));
}
__device__ __forceinline__ float2 cadd(float2 a, float2 b) { return make_float2(a.x + b.x, a.y + b.y); }
__device__ __forceinline__ float2 csub(float2 a, float2 b) { return make_float2(a.x - b.x, a.y - b.y); }
__device__ __forceinline__ float2 cconj(float2 a) { return make_float2(a.x, -a.y); }
__device__ __forceinline__ float2 mul_mi(float2 a) { return make_float2(a.y, -a.x); }  // * -i
__device__ __forceinline__ float2 mul_pi(float2 a) { return make_float2(-a.y, a.x); }  // * +i

__device__ __forceinline__ void gbar(int id) {
    asm volatile("bar.sync %0, 64;" :: "r"(id) : "memory");
}

// Natural-order DFT-8, W = exp(-2*pi*i/8)
__device__ __forceinline__ void dft8(float2 v[8]) {
    const float S = 0.70710678118654752440f;
    float2 a00 = cadd(v[0], v[4]), a01 = csub(v[0], v[4]);
    float2 a10 = cadd(v[1], v[5]), a11 = csub(v[1], v[5]);
    float2 a20 = cadd(v[2], v[6]), a21 = csub(v[2], v[6]);
    float2 a30 = cadd(v[3], v[7]), a31 = csub(v[3], v[7]);
    float2 b00 = cadd(a00, a20), b02 = csub(a00, a20);
    float2 b01 = cadd(a01, mul_mi(a21)), b03 = cadd(a01, mul_pi(a21));
    float2 b10 = cadd(a10, a30), b12 = csub(a10, a30);
    float2 b11 = cadd(a11, mul_mi(a31)), b13 = cadd(a11, mul_pi(a31));
    float2 w1b11 = make_float2(S * (b11.x + b11.y), S * (b11.y - b11.x));   // W^1 * b11
    float2 w3b13 = make_float2(S * (b13.y - b13.x), -S * (b13.x + b13.y));  // W^3 * b13
    v[0] = cadd(b00, b10);          v[4] = csub(b00, b10);
    v[1] = cadd(b01, w1b11);        v[5] = csub(b01, w1b11);
    v[2] = cadd(b02, mul_mi(b12));  v[6] = cadd(b02, mul_pi(b12));
    v[3] = cadd(b03, w3b13);        v[7] = csub(b03, w3b13);
}

// ---- DUAL register-resident Stockham radix-8 512-pt FFT ----
// Two independent FFTs (va in buffer A, vb in buffer B) share barriers and
// twiddle sincos. v[r] holds element (j + 64*r), natural order, 64 thr/group.
__device__ __forceinline__ void fft512_reg2(float2 va[8], float2 vb[8], int j,
                                            float2* A, float2* B, int barid) {
    dft8(va); dft8(vb);
    gbar(barid);
#pragma unroll
    for (int r = 0; r < 8; r++) { A[IDX(8 * j + r)] = va[r]; B[IDX(8 * j + r)] = vb[r]; }
    gbar(barid);
#pragma unroll
    for (int r = 0; r < 8; r++) { va[r] = A[IDX(j + 64 * r)]; vb[r] = B[IDX(j + 64 * r)]; }
    {   // shared stage-1 twiddle: exp(-2*pi*i*(j&7)/64)
        float ang = -6.2831853071795864769f * (float)(j & 7) * (1.0f / 64.0f);
        float s, c; __sincosf(ang, &s, &c);
        float2 w = make_float2(c, s), wr = w;
#pragma unroll
        for (int r = 1; r < 8; r++) { va[r] = cmul(va[r], wr); vb[r] = cmul(vb[r], wr); wr = cmul(wr, w); }
    }
    dft8(va); dft8(vb);
    gbar(barid);
#pragma unroll
    for (int r = 0; r < 8; r++) {
        int d = ((j >> 3) << 6) + (j & 7) + 8 * r;
        A[IDX(d)] = va[r]; B[IDX(d)] = vb[r];
    }
    gbar(barid);
#pragma unroll
    for (int r = 0; r < 8; r++) { va[r] = A[IDX(j + 64 * r)]; vb[r] = B[IDX(j + 64 * r)]; }
    {   // shared stage-2 twiddle: exp(-2*pi*i*j/512)
        float ang = -6.2831853071795864769f * (float)j * (1.0f / 512.0f);
        float s, c; __sincosf(ang, &s, &c);
        float2 w = make_float2(c, s), wr = w;
#pragma unroll
        for (int r = 1; r < 8; r++) { va[r] = cmul(va[r], wr); vb[r] = cmul(vb[r], wr); wr = cmul(wr, w); }
    }
    dft8(va); dft8(vb);
    // v[r] = X[j + 64*r]
}

// Single-stream variant (used by the final pass where FC accumulators eat registers)
__device__ __forceinline__ void fft512_reg(float2 v[8], int j, float2* A, int barid) {
    dft8(v);
    gbar(barid);
#pragma unroll
    for (int r = 0; r < 8; r++) A[IDX(8 * j + r)] = v[r];
    gbar(barid);
#pragma unroll
    for (int r = 0; r < 8; r++) v[r] = A[IDX(j + 64 * r)];
    {
        float ang = -6.2831853071795864769f * (float)(j & 7) * (1.0f / 64.0f);
        float s, c; __sincosf(ang, &s, &c);
        float2 w = make_float2(c, s), wr = w;
#pragma unroll
        for (int r = 1; r < 8; r++) { v[r] = cmul(v[r], wr); wr = cmul(wr, w); }
    }
    dft8(v);
    gbar(barid);
#pragma unroll
    for (int r = 0; r < 8; r++) A[IDX(((j >> 3) << 6) + (j & 7) + 8 * r)] = v[r];
    gbar(barid);
#pragma unroll
    for (int r = 0; r < 8; r++) v[r] = A[IDX(j + 64 * r)];
    {
        float ang = -6.2831853071795864769f * (float)j * (1.0f / 512.0f);
        float s, c; __sincosf(ang, &s, &c);
        float2 w = make_float2(c, s), wr = w;
#pragma unroll
        for (int r = 1; r < 8; r++) { v[r] = cmul(v[r], wr); wr = cmul(wr, w); }
    }
    dft8(v);
}

// ---- table init (fp64 phase to match numpy's float64 H) ----
__global__ void k_init() {
    int f = threadIdx.x;
    if (f >= RES) return;
    const double PI = 3.14159265358979323846;
    const double lam = 5.32e-07, z = 0.035, dx = 1e-06;
    double fx = ((f < RES / 2) ? (double)f : (double)(f - RES)) / ((double)RES * dx);
    double ang = -PI * lam * z * fx * fx;
    double s, c;
    sincos(ang, &s, &c);
    g_gx[f] = make_float2((float)c, (float)s);
    double kz = (2.0 * PI / lam) * z;
    double s2, c2;
    sincos(ang + kz, &s2, &c2);
    double inv = 1.0 / ((double)RES * (double)RES);
    g_gcol[f] = make_float2((float)(c2 * inv), (float)(s2 * inv));
}

// ---- phase exponential precompute: g_phexp = exp(i*phases) ----
__global__ void k_phexp(const float* __restrict__ phases) {
    size_t i = (size_t)blockIdx.x * 1024 + threadIdx.x;
    float s, c;
    __sincosf(phases[i], &s, &c);
    g_phexp[i] = make_float2(c, s);
}

// ---- layer-0 row pass (dual): x * e^{i phi0} -> FFT -> * g(fx) ----
__global__ void __launch_bounds__(128, 5)
k_row_first(const float* __restrict__ x, int row0) {
    extern __shared__ float2 sm[];
    const int g = threadIdx.x >> 6, j = threadIdx.x & 63;
    const int rowA = row0 + blockIdx.x * 4 + g * 2;
    const int yA = rowA & 511;
    const float* xrA = x + (size_t)rowA * RES;
    const float* xrB = xrA + RES;
    const float2* peA = g_phexp + (size_t)yA * RES;
    const float2* peB = peA + RES;
    float2* A = sm + (size_t)(2 * g) * BUFSZ;
    float2* B = A + BUFSZ;
    float2 va[8], vb[8];
#pragma unroll
    for (int r = 0; r < 8; r++) {
        int i = j + r * 64;
        float2 ea = peA[i], eb = peB[i];
        float xa = xrA[i], xb = xrB[i];
        va[r] = make_float2(xa * ea.x, xa * ea.y);
        vb[r] = make_float2(xb * eb.x, xb * eb.y);
    }
    fft512_reg2(va, vb, j, A, B, 1 + g);
    float2* outA = g_field + (size_t)rowA * RES;
    float2* outB = outA + RES;
#pragma unroll
    for (int r = 0; r < 8; r++) {
        int f = j + r * 64;
        float2 gx = g_gx[f];
        outA[f] = cmul(va[r], gx);
        outB[f] = cmul(vb[r], gx);
    }
}

// ---- mid row pass (dual): unnorm IFFT -> * e^{i phi} -> FFT -> * g(fx) ----
__global__ void __launch_bounds__(128, 5)
k_row_mid(int layer, int row0) {
    extern __shared__ float2 sm[];
    const int g = threadIdx.x >> 6, j = threadIdx.x & 63;
    const int rowA = row0 + blockIdx.x * 4 + g * 2;
    const int yA = rowA & 511;
    const float2* peA = g_phexp + (size_t)layer * RES * RES + (size_t)yA * RES;
    const float2* peB = peA + RES;
    float2* A = sm + (size_t)(2 * g) * BUFSZ;
    float2* B = A + BUFSZ;
    float2* inA = g_field + (size_t)rowA * RES;
    float2* inB = inA + RES;
    float2 va[8], vb[8];
#pragma unroll
    for (int r = 0; r < 8; r++) {
        int i = j + r * 64;
        va[r] = cconj(inA[i]);   // IFFT via conj-FFT-conj
        vb[r] = cconj(inB[i]);
    }
    fft512_reg2(va, vb, j, A, B, 1 + g);
#pragma unroll
    for (int r = 0; r < 8; r++) {
        int i = j + r * 64;
        va[r] = cmul(cconj(va[r]), peA[i]);
        vb[r] = cmul(cconj(vb[r]), peB[i]);
    }
    fft512_reg2(va, vb, j, A, B, 1 + g);
#pragma unroll
    for (int r = 0; r < 8; r++) {
        int f = j + r * 64;
        float2 gx = g_gx[f];
        inA[f] = cmul(va[r], gx);
        inB[f] = cmul(vb[r], gx);
    }
}

// ---- column pass (dual): FFT(col) -> * gcol -> unnorm IFFT(col), 8 cols/block ----
__global__ void __launch_bounds__(256, 3)
k_col(int b0) {
    extern __shared__ float2 sm[];
    const int tid = threadIdx.x;
    const int g = tid >> 6, j = tid & 63;
    const int b = b0 + blockIdx.x;
    const int c0 = blockIdx.y * 8;
    float2* base = g_field + (size_t)b * RES * RES + c0;
    // cooperative transposed load: 8 consecutive threads read 8 consecutive cols (64B)
#pragma unroll
    for (int i = 0; i < 16; i++) {
        int rowi = i * 32 + (tid >> 3);
        int cc = tid & 7;
        sm[(size_t)cc * BUFSZ + IDX(rowi)] = base[(size_t)rowi * RES + cc];
    }
    __syncthreads();
    float2* A = sm + (size_t)(2 * g) * BUFSZ;
    float2* B = A + BUFSZ;
    float2 va[8], vb[8];
#pragma unroll
    for (int r = 0; r < 8; r++) { va[r] = A[IDX(j + 64 * r)]; vb[r] = B[IDX(j + 64 * r)]; }
    fft512_reg2(va, vb, j, A, B, 1 + g);
#pragma unroll
    for (int r = 0; r < 8; r++) {
        int f = j + r * 64;
        float2 gc = g_gcol[f];
        va[r] = cconj(cmul(va[r], gc));
        vb[r] = cconj(cmul(vb[r], gc));
    }
    fft512_reg2(va, vb, j, A, B, 1 + g);
    // each thread rewrites exactly the slots it read in the last stage — no hazard
#pragma unroll
    for (int r = 0; r < 8; r++) {
        A[IDX(j + 64 * r)] = cconj(va[r]);
        B[IDX(j + 64 * r)] = cconj(vb[r]);
    }
    __syncthreads();
#pragma unroll
    for (int i = 0; i < 16; i++) {
        int rowi = i * 32 + (tid >> 3);
        int cc = tid & 7;
        base[(size_t)rowi * RES + cc] = sm[(size_t)cc * BUFSZ + IDX(rowi)];
    }
}

// ---- final row pass: unnorm IFFT(row) -> intensity -> per-row dot with fc_w ----
__global__ void __launch_bounds__(128, 5)
k_row_final(const float* __restrict__ fc_w, int row0) {
    extern __shared__ float2 sm[];
    __shared__ float smred[2][2][NC];
    const int g = threadIdx.x >> 6, j = threadIdx.x & 63;
    const int row = row0 + blockIdx.x * 2 + g;
    const int y = row & 511;
    float2* A = sm + (size_t)g * BUFSZ;
    float2* inrow = g_field + (size_t)row * RES;
    float2 v[8];
#pragma unroll
    for (int r = 0; r < 8; r++) v[r] = cconj(inrow[j + r * 64]);
    fft512_reg(v, j, A, 1 + g);   // |conj(.)|^2 == |.|^2, skip final conj
    float acc[NC];
#pragma unroll
    for (int c = 0; c < NC; c++) acc[c] = 0.0f;
#pragma unroll
    for (int r = 0; r < 8; r++) {
        int i = j + r * 64;
        float2 t = v[r];
        float I = t.x * t.x + t.y * t.y;
        size_t col = (size_t)y * RES + i;
#pragma unroll
        for (int c = 0; c < NC; c++) acc[c] += I * fc_w[(size_t)c * (RES * RES) + col];
    }
#pragma unroll
    for (int c = 0; c < NC; c++) {
#pragma unroll
        for (int off = 16; off > 0; off >>= 1)
            acc[c] += __shfl_down_sync(0xffffffffu, acc[c], off);
    }
    const int lane = j & 31;
    const int half = j >> 5;
    if (lane == 0) {
#pragma unroll
        for (int c = 0; c < NC; c++) smred[g][half][c] = acc[c];
    }
    __syncthreads();
    if (j < NC) g_partial[(size_t)row * NC + j] = smred[g][0][j] + smred[g][1][j];
}

// ---- final reduce: out[b][c] = fc_b[c] + sum_y partial[b*512+y][c] ----
__global__ void k_fc_reduce(const float* __restrict__ fc_b, float* __restrict__ out) {
    const int b = blockIdx.x;
    const int w = threadIdx.x >> 5;
    const int l = threadIdx.x & 31;
    if (w >= NC) return;
    float s = 0.0f;
    for (int y = l; y < RES; y += 32)
        s += g_partial[((size_t)(b << 9) + y) * NC + w];
#pragma unroll
    for (int off = 16; off > 0; off >>= 1)
        s += __shfl_down_sync(0xffffffffu, s, off);
    if (l == 0) out[b * NC + w] = s + fc_b[w];
}

extern "C" void kernel_launch(void* const* d_in, const int* in_sizes, int n_in,
                              void* d_out, int out_size) {
    (void)in_sizes; (void)n_in; (void)out_size;
    const float* x      = (const float*)d_in[0];
    const float* phases = (const float*)d_in[1];
    const float* fc_w   = (const float*)d_in[2];
    const float* fc_b   = (const float*)d_in[3];
    float* out = (float*)d_out;

    // Max shared-memory carveout so smem never caps residency (done once; cheap,
    // not a stream op — safe under graph capture).
    static int configured = 0;
    if (!configured) {
        cudaFuncSetAttribute(k_row_first, cudaFuncAttributePreferredSharedMemoryCarveout, 100);
        cudaFuncSetAttribute(k_row_mid,   cudaFuncAttributePreferredSharedMemoryCarveout, 100);
        cudaFuncSetAttribute(k_col,       cudaFuncAttributePreferredSharedMemoryCarveout, 100);
        cudaFuncSetAttribute(k_row_final, cudaFuncAttributePreferredSharedMemoryCarveout, 100);
        configured = 1;
    }

    const size_t SMEM_ROW  = (size_t)4 * BUFSZ * sizeof(float2);  // 18592 B
    const size_t SMEM_COL  = (size_t)8 * BUFSZ * sizeof(float2);  // 37184 B
    const size_t SMEM_FIN  = (size_t)2 * BUFSZ * sizeof(float2);  //  9296 B
    const int ROW_BLOCKS = CH * RES / 4;                          // 4096 per chunk
    const int FIN_BLOCKS = CH * RES / 2;                          // 8192 per chunk
    const int N_CHUNKS = BATCH / CH;                              // 4

    k_init<<<1, RES>>>();
    k_phexp<<<3 * RES * RES / 1024, 1024>>>(phases);
    // Whole 7-pass pipeline per 32-image chunk: working set stays in L2.
    for (int c = 0; c < N_CHUNKS; c++) {
        const int b0 = c * CH;
        const int row0 = b0 * RES;
        k_row_first<<<ROW_BLOCKS, 128, SMEM_ROW>>>(x, row0);
        for (int layer = 0; layer < 3; layer++) {
            k_col<<<dim3(CH, RES / 8), 256, SMEM_COL>>>(b0);
            if (layer < 2)
                k_row_mid<<<ROW_BLOCKS, 128, SMEM_ROW>>>(layer + 1, row0);
        }
        k_row_final<<<FIN_BLOCKS, 128, SMEM_FIN>>>(fc_w, row0);
    }
    k_fc_reduce<<<BATCH, 320>>>(fc_b, out);
}

// round 7
// speedup vs baseline: 1.0966x; 1.0665x over previous
#include <cuda_runtime.h>

#define RES 512
#define BATCH 128
#define NC 10
#define CH 32                      // images per chunk; 2 chunks in flight ≈ L2 size
#define BUFSZ 581                  // 576 (padded 512) + 5: buffer-to-buffer bank decorrelation
#define IDX(i) ((i) + ((i) >> 3))

// ---- device-global scratch (allocation-free rule) ----
__device__ float2 g_field[(size_t)BATCH * RES * RES];
__device__ float  g_partial[(size_t)BATCH * RES * NC];
__device__ float2 g_phexp[(size_t)3 * RES * RES];  // exp(i*phase), layer-major
__device__ float2 g_gx[RES];    // exp(-i*pi*lam*z*fx^2)
__device__ float2 g_gcol[RES];  // exp(i*K*Z)*exp(-i*pi*lam*z*fy^2) / (RES*RES)

__device__ __forceinline__ float2 cmul(float2 a, float2 b) {
    return make_float2(fmaf(a.x, b.x, -a.y * b.y), fmaf(a.x, b.y, a.y * b.x));
}
__device__ __forceinline__ float2 cadd(float2 a, float2 b) { return make_float2(a.x + b.x, a.y + b.y); }
__device__ __forceinline__ float2 csub(float2 a, float2 b) { return make_float2(a.x - b.x, a.y - b.y); }
__device__ __forceinline__ float2 cconj(float2 a) { return make_float2(a.x, -a.y); }
__device__ __forceinline__ float2 mul_mi(float2 a) { return make_float2(a.y, -a.x); }  // * -i
__device__ __forceinline__ float2 mul_pi(float2 a) { return make_float2(-a.y, a.x); }  // * +i

__device__ __forceinline__ void gbar(int id) {
    asm volatile("bar.sync %0, 64;" :: "r"(id) : "memory");
}

// Natural-order DFT-8, W = exp(-2*pi*i/8)
__device__ __forceinline__ void dft8(float2 v[8]) {
    const float S = 0.70710678118654752440f;
    float2 a00 = cadd(v[0], v[4]), a01 = csub(v[0], v[4]);
    float2 a10 = cadd(v[1], v[5]), a11 = csub(v[1], v[5]);
    float2 a20 = cadd(v[2], v[6]), a21 = csub(v[2], v[6]);
    float2 a30 = cadd(v[3], v[7]), a31 = csub(v[3], v[7]);
    float2 b00 = cadd(a00, a20), b02 = csub(a00, a20);
    float2 b01 = cadd(a01, mul_mi(a21)), b03 = cadd(a01, mul_pi(a21));
    float2 b10 = cadd(a10, a30), b12 = csub(a10, a30);
    float2 b11 = cadd(a11, mul_mi(a31)), b13 = cadd(a11, mul_pi(a31));
    float2 w1b11 = make_float2(S * (b11.x + b11.y), S * (b11.y - b11.x));   // W^1 * b11
    float2 w3b13 = make_float2(S * (b13.y - b13.x), -S * (b13.x + b13.y));  // W^3 * b13
    v[0] = cadd(b00, b10);          v[4] = csub(b00, b10);
    v[1] = cadd(b01, w1b11);        v[5] = csub(b01, w1b11);
    v[2] = cadd(b02, mul_mi(b12));  v[6] = cadd(b02, mul_pi(b12));
    v[3] = cadd(b03, w3b13);        v[7] = csub(b03, w3b13);
}

// ---- DUAL register-resident Stockham radix-8 512-pt FFT ----
// Two independent FFTs (va in buffer A, vb in buffer B) share barriers and
// twiddle sincos. v[r] holds element (j + 64*r), natural order, 64 thr/group.
__device__ __forceinline__ void fft512_reg2(float2 va[8], float2 vb[8], int j,
                                            float2* A, float2* B, int barid) {
    dft8(va); dft8(vb);
    gbar(barid);
#pragma unroll
    for (int r = 0; r < 8; r++) { A[IDX(8 * j + r)] = va[r]; B[IDX(8 * j + r)] = vb[r]; }
    gbar(barid);
#pragma unroll
    for (int r = 0; r < 8; r++) { va[r] = A[IDX(j + 64 * r)]; vb[r] = B[IDX(j + 64 * r)]; }
    {   // shared stage-1 twiddle: exp(-2*pi*i*(j&7)/64)
        float ang = -6.2831853071795864769f * (float)(j & 7) * (1.0f / 64.0f);
        float s, c; __sincosf(ang, &s, &c);
        float2 w = make_float2(c, s), wr = w;
#pragma unroll
        for (int r = 1; r < 8; r++) { va[r] = cmul(va[r], wr); vb[r] = cmul(vb[r], wr); wr = cmul(wr, w); }
    }
    dft8(va); dft8(vb);
    gbar(barid);
#pragma unroll
    for (int r = 0; r < 8; r++) {
        int d = ((j >> 3) << 6) + (j & 7) + 8 * r;
        A[IDX(d)] = va[r]; B[IDX(d)] = vb[r];
    }
    gbar(barid);
#pragma unroll
    for (int r = 0; r < 8; r++) { va[r] = A[IDX(j + 64 * r)]; vb[r] = B[IDX(j + 64 * r)]; }
    {   // shared stage-2 twiddle: exp(-2*pi*i*j/512)
        float ang = -6.2831853071795864769f * (float)j * (1.0f / 512.0f);
        float s, c; __sincosf(ang, &s, &c);
        float2 w = make_float2(c, s), wr = w;
#pragma unroll
        for (int r = 1; r < 8; r++) { va[r] = cmul(va[r], wr); vb[r] = cmul(vb[r], wr); wr = cmul(wr, w); }
    }
    dft8(va); dft8(vb);
    // v[r] = X[j + 64*r]
}

// Single-stream variant (used by the final pass where FC accumulators eat registers)
__device__ __forceinline__ void fft512_reg(float2 v[8], int j, float2* A, int barid) {
    dft8(v);
    gbar(barid);
#pragma unroll
    for (int r = 0; r < 8; r++) A[IDX(8 * j + r)] = v[r];
    gbar(barid);
#pragma unroll
    for (int r = 0; r < 8; r++) v[r] = A[IDX(j + 64 * r)];
    {
        float ang = -6.2831853071795864769f * (float)(j & 7) * (1.0f / 64.0f);
        float s, c; __sincosf(ang, &s, &c);
        float2 w = make_float2(c, s), wr = w;
#pragma unroll
        for (int r = 1; r < 8; r++) { v[r] = cmul(v[r], wr); wr = cmul(wr, w); }
    }
    dft8(v);
    gbar(barid);
#pragma unroll
    for (int r = 0; r < 8; r++) A[IDX(((j >> 3) << 6) + (j & 7) + 8 * r)] = v[r];
    gbar(barid);
#pragma unroll
    for (int r = 0; r < 8; r++) v[r] = A[IDX(j + 64 * r)];
    {
        float ang = -6.2831853071795864769f * (float)j * (1.0f / 512.0f);
        float s, c; __sincosf(ang, &s, &c);
        float2 w = make_float2(c, s), wr = w;
#pragma unroll
        for (int r = 1; r < 8; r++) { v[r] = cmul(v[r], wr); wr = cmul(wr, w); }
    }
    dft8(v);
}

// ---- table init (fp64 phase to match numpy's float64 H) ----
__global__ void k_init() {
    int f = threadIdx.x;
    if (f >= RES) return;
    const double PI = 3.14159265358979323846;
    const double lam = 5.32e-07, z = 0.035, dx = 1e-06;
    double fx = ((f < RES / 2) ? (double)f : (double)(f - RES)) / ((double)RES * dx);
    double ang = -PI * lam * z * fx * fx;
    double s, c;
    sincos(ang, &s, &c);
    g_gx[f] = make_float2((float)c, (float)s);
    double kz = (2.0 * PI / lam) * z;
    double s2, c2;
    sincos(ang + kz, &s2, &c2);
    double inv = 1.0 / ((double)RES * (double)RES);
    g_gcol[f] = make_float2((float)(c2 * inv), (float)(s2 * inv));
}

// ---- phase exponential precompute: g_phexp = exp(i*phases) ----
__global__ void k_phexp(const float* __restrict__ phases) {
    size_t i = (size_t)blockIdx.x * 1024 + threadIdx.x;
    float s, c;
    __sincosf(phases[i], &s, &c);
    g_phexp[i] = make_float2(c, s);
}

// ---- layer-0 row pass (dual): x * e^{i phi0} -> FFT -> * g(fx) ----
__global__ void __launch_bounds__(128, 4)
k_row_first(const float* __restrict__ x, int row0) {
    extern __shared__ float2 sm[];
    const int g = threadIdx.x >> 6, j = threadIdx.x & 63;
    const int rowA = row0 + blockIdx.x * 4 + g * 2;
    const int yA = rowA & 511;
    const float* xrA = x + (size_t)rowA * RES;
    const float* xrB = xrA + RES;
    const float2* peA = g_phexp + (size_t)yA * RES;
    const float2* peB = peA + RES;
    float2* A = sm + (size_t)(2 * g) * BUFSZ;
    float2* B = A + BUFSZ;
    float2 va[8], vb[8];
#pragma unroll
    for (int r = 0; r < 8; r++) {
        int i = j + r * 64;
        float2 ea = peA[i], eb = peB[i];
        float xa = xrA[i], xb = xrB[i];
        va[r] = make_float2(xa * ea.x, xa * ea.y);
        vb[r] = make_float2(xb * eb.x, xb * eb.y);
    }
    fft512_reg2(va, vb, j, A, B, 1 + g);
    float2* outA = g_field + (size_t)rowA * RES;
    float2* outB = outA + RES;
#pragma unroll
    for (int r = 0; r < 8; r++) {
        int f = j + r * 64;
        float2 gx = g_gx[f];
        outA[f] = cmul(va[r], gx);
        outB[f] = cmul(vb[r], gx);
    }
}

// ---- mid row pass (dual): unnorm IFFT -> * e^{i phi} -> FFT -> * g(fx) ----
__global__ void __launch_bounds__(128, 4)
k_row_mid(int layer, int row0) {
    extern __shared__ float2 sm[];
    const int g = threadIdx.x >> 6, j = threadIdx.x & 63;
    const int rowA = row0 + blockIdx.x * 4 + g * 2;
    const int yA = rowA & 511;
    const float2* peA = g_phexp + (size_t)layer * RES * RES + (size_t)yA * RES;
    const float2* peB = peA + RES;
    float2* A = sm + (size_t)(2 * g) * BUFSZ;
    float2* B = A + BUFSZ;
    float2* inA = g_field + (size_t)rowA * RES;
    float2* inB = inA + RES;
    float2 va[8], vb[8];
#pragma unroll
    for (int r = 0; r < 8; r++) {
        int i = j + r * 64;
        va[r] = cconj(inA[i]);   // IFFT via conj-FFT-conj
        vb[r] = cconj(inB[i]);
    }
    fft512_reg2(va, vb, j, A, B, 1 + g);
#pragma unroll
    for (int r = 0; r < 8; r++) {
        int i = j + r * 64;
        va[r] = cmul(cconj(va[r]), peA[i]);
        vb[r] = cmul(cconj(vb[r]), peB[i]);
    }
    fft512_reg2(va, vb, j, A, B, 1 + g);
#pragma unroll
    for (int r = 0; r < 8; r++) {
        int f = j + r * 64;
        float2 gx = g_gx[f];
        inA[f] = cmul(va[r], gx);
        inB[f] = cmul(vb[r], gx);
    }
}

// ---- column pass (dual): FFT(col) -> * gcol -> unnorm IFFT(col), 8 cols/block ----
__global__ void __launch_bounds__(256, 2)
k_col(int b0) {
    extern __shared__ float2 sm[];
    const int tid = threadIdx.x;
    const int g = tid >> 6, j = tid & 63;
    const int b = b0 + blockIdx.x;
    const int c0 = blockIdx.y * 8;
    float2* base = g_field + (size_t)b * RES * RES + c0;
    // cooperative transposed load: 8 consecutive threads read 8 consecutive cols (64B)
#pragma unroll
    for (int i = 0; i < 16; i++) {
        int rowi = i * 32 + (tid >> 3);
        int cc = tid & 7;
        sm[(size_t)cc * BUFSZ + IDX(rowi)] = base[(size_t)rowi * RES + cc];
    }
    __syncthreads();
    float2* A = sm + (size_t)(2 * g) * BUFSZ;
    float2* B = A + BUFSZ;
    float2 va[8], vb[8];
#pragma unroll
    for (int r = 0; r < 8; r++) { va[r] = A[IDX(j + 64 * r)]; vb[r] = B[IDX(j + 64 * r)]; }
    fft512_reg2(va, vb, j, A, B, 1 + g);
#pragma unroll
    for (int r = 0; r < 8; r++) {
        int f = j + r * 64;
        float2 gc = g_gcol[f];
        va[r] = cconj(cmul(va[r], gc));
        vb[r] = cconj(cmul(vb[r], gc));
    }
    fft512_reg2(va, vb, j, A, B, 1 + g);
    // each thread rewrites exactly the slots it read in the last stage — no hazard
#pragma unroll
    for (int r = 0; r < 8; r++) {
        A[IDX(j + 64 * r)] = cconj(va[r]);
        B[IDX(j + 64 * r)] = cconj(vb[r]);
    }
    __syncthreads();
#pragma unroll
    for (int i = 0; i < 16; i++) {
        int rowi = i * 32 + (tid >> 3);
        int cc = tid & 7;
        base[(size_t)rowi * RES + cc] = sm[(size_t)cc * BUFSZ + IDX(rowi)];
    }
}

// ---- final row pass: unnorm IFFT(row) -> intensity -> per-row dot with fc_w ----
__global__ void __launch_bounds__(128, 4)
k_row_final(const float* __restrict__ fc_w, int row0) {
    extern __shared__ float2 sm[];
    __shared__ float smred[2][2][NC];
    const int g = threadIdx.x >> 6, j = threadIdx.x & 63;
    const int row = row0 + blockIdx.x * 2 + g;
    const int y = row & 511;
    float2* A = sm + (size_t)g * BUFSZ;
    float2* inrow = g_field + (size_t)row * RES;
    float2 v[8];
#pragma unroll
    for (int r = 0; r < 8; r++) v[r] = cconj(inrow[j + r * 64]);
    fft512_reg(v, j, A, 1 + g);   // |conj(.)|^2 == |.|^2, skip final conj
    float acc[NC];
#pragma unroll
    for (int c = 0; c < NC; c++) acc[c] = 0.0f;
#pragma unroll
    for (int r = 0; r < 8; r++) {
        int i = j + r * 64;
        float2 t = v[r];
        float I = t.x * t.x + t.y * t.y;
        size_t col = (size_t)y * RES + i;
#pragma unroll
        for (int c = 0; c < NC; c++) acc[c] += I * fc_w[(size_t)c * (RES * RES) + col];
    }
#pragma unroll
    for (int c = 0; c < NC; c++) {
#pragma unroll
        for (int off = 16; off > 0; off >>= 1)
            acc[c] += __shfl_down_sync(0xffffffffu, acc[c], off);
    }
    const int lane = j & 31;
    const int half = j >> 5;
    if (lane == 0) {
#pragma unroll
        for (int c = 0; c < NC; c++) smred[g][half][c] = acc[c];
    }
    __syncthreads();
    if (j < NC) g_partial[(size_t)row * NC + j] = smred[g][0][j] + smred[g][1][j];
}

// ---- final reduce: out[b][c] = fc_b[c] + sum_y partial[b*512+y][c] ----
__global__ void k_fc_reduce(const float* __restrict__ fc_b, float* __restrict__ out) {
    const int b = blockIdx.x;
    const int w = threadIdx.x >> 5;
    const int l = threadIdx.x & 31;
    if (w >= NC) return;
    float s = 0.0f;
    for (int y = l; y < RES; y += 32)
        s += g_partial[((size_t)(b << 9) + y) * NC + w];
#pragma unroll
    for (int off = 16; off > 0; off >>= 1)
        s += __shfl_down_sync(0xffffffffu, s, off);
    if (l == 0) out[b * NC + w] = s + fc_b[w];
}

extern "C" void kernel_launch(void* const* d_in, const int* in_sizes, int n_in,
                              void* d_out, int out_size) {
    (void)in_sizes; (void)n_in; (void)out_size;
    const float* x      = (const float*)d_in[0];
    const float* phases = (const float*)d_in[1];
    const float* fc_w   = (const float*)d_in[2];
    const float* fc_b   = (const float*)d_in[3];
    float* out = (float*)d_out;

    // One-time host-side setup: smem carveout + 2 worker streams + fork/join
    // events (host object creation only — no device memory, graph-capture safe).
    static int configured = 0;
    static cudaStream_t strm[2];
    static cudaEvent_t evFork, evJoin[2];
    if (!configured) {
        cudaFuncSetAttribute(k_row_first, cudaFuncAttributePreferredSharedMemoryCarveout, 100);
        cudaFuncSetAttribute(k_row_mid,   cudaFuncAttributePreferredSharedMemoryCarveout, 100);
        cudaFuncSetAttribute(k_col,       cudaFuncAttributePreferredSharedMemoryCarveout, 100);
        cudaFuncSetAttribute(k_row_final, cudaFuncAttributePreferredSharedMemoryCarveout, 100);
        cudaStreamCreateWithFlags(&strm[0], cudaStreamNonBlocking);
        cudaStreamCreateWithFlags(&strm[1], cudaStreamNonBlocking);
        cudaEventCreateWithFlags(&evFork,    cudaEventDisableTiming);
        cudaEventCreateWithFlags(&evJoin[0], cudaEventDisableTiming);
        cudaEventCreateWithFlags(&evJoin[1], cudaEventDisableTiming);
        configured = 1;
    }

    const size_t SMEM_ROW  = (size_t)4 * BUFSZ * sizeof(float2);  // 18592 B
    const size_t SMEM_COL  = (size_t)8 * BUFSZ * sizeof(float2);  // 37184 B
    const size_t SMEM_FIN  = (size_t)2 * BUFSZ * sizeof(float2);  //  9296 B
    const int ROW_BLOCKS = CH * RES / 4;                          // 4096 per chunk
    const int FIN_BLOCKS = CH * RES / 2;                          // 8192 per chunk
    const int N_CHUNKS = BATCH / CH;                              // 4

    // Tables on the default (captured-origin) stream.
    k_init<<<1, RES>>>();
    k_phexp<<<3 * RES * RES / 1024, 1024>>>(phases);

    // Fork: both worker streams wait for table init.
    cudaEventRecord(evFork, 0);
    cudaStreamWaitEvent(strm[0], evFork, 0);
    cudaStreamWaitEvent(strm[1], evFork, 0);

    // Two chunk pipelines in flight (chunks alternate across the 2 streams;
    // each stream runs its chunks serially). Independent images → no deps.
    for (int c = 0; c < N_CHUNKS; c++) {
        cudaStream_t s = strm[c & 1];
        const int b0 = c * CH;
        const int row0 = b0 * RES;
        k_row_first<<<ROW_BLOCKS, 128, SMEM_ROW, s>>>(x, row0);
        for (int layer = 0; layer < 3; layer++) {
            k_col<<<dim3(CH, RES / 8), 256, SMEM_COL, s>>>(b0);
            if (layer < 2)
                k_row_mid<<<ROW_BLOCKS, 128, SMEM_ROW, s>>>(layer + 1, row0);
        }
        k_row_final<<<FIN_BLOCKS, 128, SMEM_FIN, s>>>(fc_w, row0);
    }

    // Join back to the default stream, then reduce.
    cudaEventRecord(evJoin[0], strm[0]);
    cudaEventRecord(evJoin[1], strm[1]);
    cudaStreamWaitEvent(0, evJoin[0], 0);
    cudaStreamWaitEvent(0, evJoin[1], 0);
    k_fc_reduce<<<BATCH, 320>>>(fc_b, out);
}